// round 14
// baseline (speedup 1.0000x reference)
#include <cuda_runtime.h>
#include <math.h>

__device__ float g_Q[512 * 192];
__device__ float g_K[512 * 192];
__device__ float g_V[512 * 192];
__device__ float g_QP[512 * 144];
__device__ float g_KP[512 * 144];
__device__ float g_VP[512 * 288];
__device__ float g_QG[512 * 144];
__device__ float g_KG[512 * 144];
__device__ float g_VG[512 * 288];
__device__ float g_VT[192 * 512];               // V transposed  [c][m]
__device__ float g_VGT[288 * 512];              // VG transposed [c][m]
__device__ float g_F[512 * 2112];               // feats  [n][h*176 + f]
__device__ float g_EP[4 * 512 * 384];           // split-K partials

// ---------------- kProj: fused projection GEMM, 512 x 1152, K=384 (validated) ----------------
__device__ __forceinline__ void segSelW(int c,
    const float* Wq, const float* Wk, const float* Wv,
    const float* Wqp, const float* Wkp, const float* Wvp,
    const float*& W, int& lc, int& sn)
{
    if (c < 192)      { W = Wq;  lc = c;       sn = 192; }
    else if (c < 384) { W = Wk;  lc = c - 192; sn = 192; }
    else if (c < 576) { W = Wv;  lc = c - 384; sn = 192; }
    else if (c < 720) { W = Wqp; lc = c - 576; sn = 144; }
    else if (c < 864) { W = Wkp; lc = c - 720; sn = 144; }
    else              { W = Wvp; lc = c - 864; sn = 288; }
}

__device__ __forceinline__ void segSelO(int c,
    const float* bq, const float* bk, const float* bv,
    const float* bqp, const float* bkp, const float* bvp,
    float*& out, const float*& bia, int& lc, int& sn)
{
    if (c < 192)      { out = g_Q;  bia = bq;  lc = c;       sn = 192; }
    else if (c < 384) { out = g_K;  bia = bk;  lc = c - 192; sn = 192; }
    else if (c < 576) { out = g_V;  bia = bv;  lc = c - 384; sn = 192; }
    else if (c < 720) { out = g_QP; bia = bqp; lc = c - 576; sn = 144; }
    else if (c < 864) { out = g_KP; bia = bkp; lc = c - 720; sn = 144; }
    else              { out = g_VP; bia = bvp; lc = c - 864; sn = 288; }
}

__global__ void __launch_bounds__(256) kProj(
    const float* __restrict__ s,
    const float* __restrict__ Wq,  const float* __restrict__ bq,
    const float* __restrict__ Wk,  const float* __restrict__ bk,
    const float* __restrict__ Wv,  const float* __restrict__ bv,
    const float* __restrict__ Wqp, const float* __restrict__ bqp,
    const float* __restrict__ Wkp, const float* __restrict__ bkp,
    const float* __restrict__ Wvp, const float* __restrict__ bvp)
{
    __shared__ float As[32 * 68];
    __shared__ float Bs[32 * 68];
    const int t  = threadIdx.x;
    const int c0 = blockIdx.x * 64;
    const int r0 = blockIdx.y * 64;
    const int tx = t % 16, ty = t / 16;

    float acc[4][4];
    #pragma unroll
    for (int i = 0; i < 4; i++)
        #pragma unroll
        for (int j = 0; j < 4; j++) acc[i][j] = 0.f;

    for (int kt = 0; kt < 384; kt += 32) {
        __syncthreads();
        #pragma unroll
        for (int ii = 0; ii < 2; ii++) {
            int i4 = t + 256 * ii;
            int row = i4 >> 3, kq = i4 & 7;
            float4 a = *(const float4*)(s + (size_t)(r0 + row) * 384 + kt + kq * 4);
            As[(kq * 4 + 0) * 68 + row] = a.x;
            As[(kq * 4 + 1) * 68 + row] = a.y;
            As[(kq * 4 + 2) * 68 + row] = a.z;
            As[(kq * 4 + 3) * 68 + row] = a.w;
        }
        #pragma unroll
        for (int ii = 0; ii < 8; ii++) {
            int i = t + 256 * ii;
            int k = i >> 6, c = i & 63;
            const float* W; int lc, sn;
            segSelW(c0 + c, Wq, Wk, Wv, Wqp, Wkp, Wvp, W, lc, sn);
            Bs[k * 68 + c] = W[(size_t)(kt + k) * sn + lc];
        }
        __syncthreads();
        #pragma unroll
        for (int k = 0; k < 32; k++) {
            float4 a = *(const float4*)&As[k * 68 + ty * 4];
            float4 b = *(const float4*)&Bs[k * 68 + tx * 4];
            float av[4] = {a.x, a.y, a.z, a.w};
            float bw[4] = {b.x, b.y, b.z, b.w};
            #pragma unroll
            for (int i = 0; i < 4; i++)
                #pragma unroll
                for (int j = 0; j < 4; j++) acc[i][j] += av[i] * bw[j];
        }
    }
    float* out; const float* bia; int lc, sn;
    segSelO(c0 + tx * 4, bq, bk, bv, bqp, bkp, bvp, out, bia, lc, sn);
    float b0 = bia[lc], b1 = bia[lc + 1], b2 = bia[lc + 2], b3 = bia[lc + 3];
    #pragma unroll
    for (int i = 0; i < 4; i++) {
        int row = r0 + ty * 4 + i;
        float4 v = {acc[i][0] + b0, acc[i][1] + b1, acc[i][2] + b2, acc[i][3] + b3};
        *(float4*)(out + (size_t)row * sn + lc) = v;
    }
}

// ---------------- pTrans (validated) ----------------
__global__ void pTrans(const float* __restrict__ trans, const float* __restrict__ rot)
{
    const int n = blockIdx.x, t = threadIdx.x;   // 192 threads
    const float* R = rot + n * 9;
    const float T0 = trans[n * 3], T1 = trans[n * 3 + 1], T2 = trans[n * 3 + 2];
    const float* src; float* dst; int li;
    if (t < 48)      { src = g_QP + n * 144; dst = g_QG + n * 144; li = t; }
    else if (t < 96) { src = g_KP + n * 144; dst = g_KG + n * 144; li = t - 48; }
    else             { src = g_VP + n * 288; dst = g_VG + n * 288; li = t - 96; }
    float p0 = src[li * 3], p1 = src[li * 3 + 1], p2 = src[li * 3 + 2];
    dst[li * 3 + 0] = R[0] * p0 + R[1] * p1 + R[2] * p2 + T0;
    dst[li * 3 + 1] = R[3] * p0 + R[4] * p1 + R[5] * p2 + T1;
    dst[li * 3 + 2] = R[6] * p0 + R[7] * p1 + R[8] * p2 + T2;
}

// ---------------- kT: transpose V (512x192) and VG (512x288) ----------------
__global__ void __launch_bounds__(256) kT()
{
    __shared__ float tile[32][33];
    const int which = blockIdx.z;
    const float* src = which ? g_VG : g_V;
    float* dst = which ? g_VGT : g_VT;
    const int C = which ? 288 : 192;
    const int m0 = blockIdx.x * 32;
    const int c0 = blockIdx.y * 32;
    if (c0 >= C) return;
    const int tx = threadIdx.x & 31, ty = threadIdx.x >> 5;   // 32 x 8
    #pragma unroll
    for (int i = ty; i < 32; i += 8)
        tile[i][tx] = src[(size_t)(m0 + i) * C + c0 + tx];
    __syncthreads();
    #pragma unroll
    for (int i = ty; i < 32; i += 8)
        dst[(size_t)(c0 + i) * 512 + m0 + tx] = tile[tx][i];
}

// ---------------- kFuse: logits + online softmax + apply, z read once (r10 validated) ----------------
__device__ __forceinline__ void cpAsync16(float* dst, const float* src)
{
    unsigned d = (unsigned)__cvta_generic_to_shared(dst);
    asm volatile("cp.async.cg.shared.global [%0], [%1], 16;" :: "r"(d), "l"(src));
}
#define CP_COMMIT() asm volatile("cp.async.commit_group;")
#define CP_WAIT1()  asm volatile("cp.async.wait_group 1;")
#define CP_WAIT0()  asm volatile("cp.async.wait_group 0;")

__global__ void __launch_bounds__(512) kFuse(
    const float* __restrict__ z, const float* __restrict__ trans,
    const float* __restrict__ rot,
    const float* __restrict__ Wb, const float* __restrict__ bb,
    const float* __restrict__ de, const float* __restrict__ sl,
    const float* __restrict__ hw)
{
    __shared__ float zt[2 * 4224];   // 32 rows x 132 (padded)
    __shared__ float lt[416];        // 32 x 13 (padded): logits -> probs
    __shared__ float q[192], qg[144], sWb[1536], sde[768];
    __shared__ float ph[36], shw[12], sbb[12], sfac[12], rmx[12], rsm[12];

    const int n = blockIdx.x, t = threadIdx.x;

    for (int i = t; i < 192; i += 512) q[i]  = g_Q[(size_t)n * 192 + i];
    for (int i = t; i < 144; i += 512) qg[i] = g_QG[(size_t)n * 144 + i];
    for (int i = t; i < 1536; i += 512) sWb[i] = Wb[i];
    for (int i = t; i < 768; i += 512) sde[i] = de[i];
    if (t < 12) {
        shw[t] = hw[t];
        sbb[t] = bb[t];
        rmx[t] = -1e30f;
        rsm[t] = 0.f;
        float a = sl[t], b2 = sl[12 + t], c = sl[24 + t];
        float mx = fmaxf(a, fmaxf(b2, c));
        float ea = expf(a - mx), eb = expf(b2 - mx), ec = expf(c - mx);
        float inv = 1.f / (ea + eb + ec);
        ph[t] = ea * inv; ph[12 + t] = eb * inv; ph[24 + t] = ec * inv;
    }
    const float tn0 = trans[n * 3], tn1 = trans[n * 3 + 1], tn2 = trans[n * 3 + 2];

    // prefetch tile 0
    {
        const int i4a = t, i4b = t + 512;
        int mm = i4a >> 5, c4 = i4a & 31;
        cpAsync16(&zt[mm * 132 + c4 * 4], z + ((size_t)n * 512 + mm) * 128 + c4 * 4);
        mm = i4b >> 5; c4 = i4b & 31;
        cpAsync16(&zt[mm * 132 + c4 * 4], z + ((size_t)n * 512 + mm) * 128 + c4 * 4);
        CP_COMMIT();
    }
    __syncthreads();

    // roles (validated r10 mapping)
    const int wid = t >> 5, lane = t & 31;
    const int hb = (t >> 5) * 3;        // pair head base (t<128)
    const int cq = lane * 4;            // pair cols
    float pacc[3][4];
    #pragma unroll
    for (int i = 0; i < 3; i++)
        #pragma unroll
        for (int j = 0; j < 4; j++) pacc[i][j] = 0.f;
    const int js = t - 128;             // scalar lane
    const int hs = (js >= 0) ? js / 16 : 0;
    float sacc = 0.f;
    const int jp = t - 320;             // pts lane
    const int hp = (jp >= 0) ? jp / 8 : 0;
    float a0 = 0.f, a1 = 0.f, a2 = 0.f;
    const int Lmm = t / 12, Lh = t % 12;   // phase-L slot (t<384)

    for (int mt = 0; mt < 16; mt++) {
        const int m0 = mt * 32;
        const int cur = mt & 1;
        float* ztc = zt + cur * 4224;
        if (mt < 15) {
            float* ztn = zt + (1 - cur) * 4224;
            const int mb = m0 + 32;
            int mm = t >> 5, c4 = t & 31;
            cpAsync16(&ztn[mm * 132 + c4 * 4], z + ((size_t)n * 512 + mb + mm) * 128 + c4 * 4);
            mm = (t + 512) >> 5; c4 = t & 31;
            cpAsync16(&ztn[mm * 132 + c4 * 4], z + ((size_t)n * 512 + mb + mm) * 128 + c4 * 4);
            CP_COMMIT();
            CP_WAIT1();
        } else {
            CP_WAIT0();
        }
        __syncthreads();

        // ---- phase L: logits for 32 m x 12 h (validated formulas) ----
        if (t < 384) {
            const int m = m0 + Lmm;
            float pb = sbb[Lh];
            #pragma unroll 8
            for (int c4 = 0; c4 < 32; c4++) {
                float4 zz = *(const float4*)&ztc[Lmm * 132 + c4 * 4];
                const float* w = &sWb[c4 * 48];
                pb += zz.x * w[Lh] + zz.y * w[12 + Lh] + zz.z * w[24 + Lh] + zz.w * w[36 + Lh];
            }
            float dx = tn0 - trans[m * 3];
            float dy = tn1 - trans[m * 3 + 1];
            float dz = tn2 - trans[m * 3 + 2];
            float d  = sqrtf(dx * dx + dy * dy + dz * dz);
            int bin = min(max((int)ceilf(d * 2.0f) - 1, 0), 63);
            float lo = (d <= 5.0f) ? 1.f : 0.f;
            float me = (d > 5.0f && d <= 15.0f) ? 1.f : 0.f;
            const float* kr = g_K  + (size_t)m * 192 + Lh * 16;
            const float* kg = g_KG + (size_t)m * 144 + Lh * 12;
            float sc = 0.f;
            #pragma unroll
            for (int c = 0; c < 16; c++) sc += q[Lh * 16 + c] * kr[c];
            float pd = 0.f;
            #pragma unroll
            for (int i = 0; i < 12; i++) {
                float df = qg[Lh * 12 + i] - kg[i];
                pd += df * df;
            }
            lt[Lmm * 13 + Lh] = 0.25f * sc - 0.5f * pd * shw[Lh] + pb
                              + sde[bin * 12 + Lh] + lo * ph[Lh] + me * ph[12 + Lh] + ph[24 + Lh];
        }
        __syncthreads();

        // ---- phase S: online softmax update, warp per head ----
        if (wid < 12) {
            const int h = wid;
            float l = lt[lane * 13 + h];
            float tmax = l;
            #pragma unroll
            for (int o = 16; o; o >>= 1) tmax = fmaxf(tmax, __shfl_xor_sync(0xffffffffu, tmax, o));
            float om = rmx[h];
            float nm = fmaxf(om, tmax);
            float p = expf(l - nm);
            float tsum = p;
            #pragma unroll
            for (int o = 16; o; o >>= 1) tsum += __shfl_xor_sync(0xffffffffu, tsum, o);
            float f = expf(om - nm);
            lt[lane * 13 + h] = p;
            if (lane == 0) {
                rmx[h] = nm;
                rsm[h] = rsm[h] * f + tsum;
                sfac[h] = f;
            }
        }
        __syncthreads();

        // ---- phase A: rescale + accumulate (transposed V/VG reads) ----
        if (t < 128) {
            #pragma unroll
            for (int hh = 0; hh < 3; hh++) {
                float f = sfac[hb + hh];
                #pragma unroll
                for (int j = 0; j < 4; j++) pacc[hh][j] *= f;
            }
            #pragma unroll 8
            for (int mm = 0; mm < 32; mm++) {
                float4 zz = *(const float4*)&ztc[mm * 132 + cq];
                #pragma unroll
                for (int hh = 0; hh < 3; hh++) {
                    float p = lt[mm * 13 + hb + hh];
                    pacc[hh][0] += p * zz.x; pacc[hh][1] += p * zz.y;
                    pacc[hh][2] += p * zz.z; pacc[hh][3] += p * zz.w;
                }
            }
        } else if (t < 320) {
            sacc *= sfac[hs];
            const float* vtc = g_VT + (size_t)js * 512 + m0;   // contiguous in m
            #pragma unroll 8
            for (int mm = 0; mm < 32; mm++)
                sacc += lt[mm * 13 + hs] * vtc[mm];
        } else if (t < 416) {
            float f = sfac[hp];
            a0 *= f; a1 *= f; a2 *= f;
            const float* v0 = g_VGT + (size_t)(jp * 3 + 0) * 512 + m0;
            const float* v1 = g_VGT + (size_t)(jp * 3 + 1) * 512 + m0;
            const float* v2 = g_VGT + (size_t)(jp * 3 + 2) * 512 + m0;
            #pragma unroll 8
            for (int mm = 0; mm < 32; mm++) {
                float pm = lt[mm * 13 + hp];
                a0 += pm * v0[mm]; a1 += pm * v1[mm]; a2 += pm * v2[mm];
            }
        }
        __syncthreads();
    }

    // epilogue (validated)
    if (t < 12) sfac[t] = 1.0f / rsm[t];
    __syncthreads();
    if (t < 128) {
        #pragma unroll
        for (int hh = 0; hh < 3; hh++) {
            float inv = sfac[hb + hh];
            float4 v = {pacc[hh][0] * inv, pacc[hh][1] * inv,
                        pacc[hh][2] * inv, pacc[hh][3] * inv};
            *(float4*)(g_F + (size_t)n * 2112 + (hb + hh) * 176 + 48 + cq) = v;
        }
    } else if (t < 320) {
        g_F[(size_t)n * 2112 + hs * 176 + (js % 16)] = sacc * sfac[hs];
    } else if (t < 416) {
        const int pp = jp % 8;
        float inv = sfac[hp];
        a0 = a0 * inv - tn0; a1 = a1 * inv - tn1; a2 = a2 * inv - tn2;
        const float* R = rot + n * 9;
        float lx = R[0] * a0 + R[3] * a1 + R[6] * a2;   // R^T
        float ly = R[1] * a0 + R[4] * a1 + R[7] * a2;
        float lz = R[2] * a0 + R[5] * a1 + R[8] * a2;
        float* Fh = g_F + (size_t)n * 2112 + hp * 176;
        Fh[16 + pp * 3]     = lx;
        Fh[16 + pp * 3 + 1] = ly;
        Fh[16 + pp * 3 + 2] = lz;
        Fh[40 + pp]         = sqrtf(lx * lx + ly * ly + lz * lz);
    }
}

// ---------------- kOut: tiled split-K GEMM 512x384, K=2112 (validated, splitK 4) ----------------
__global__ void __launch_bounds__(256) kOut(const float* __restrict__ Wout)
{
    __shared__ float As[16 * 68];
    __shared__ float Bs[16 * 68];
    const int t  = threadIdx.x;
    const int c0 = blockIdx.x * 64;
    const int r0 = blockIdx.y * 64;
    const int k0 = blockIdx.z * 528;
    const int tx = t % 16, ty = t / 16;
    float acc[4][4];
    #pragma unroll
    for (int i = 0; i < 4; i++)
        #pragma unroll
        for (int j = 0; j < 4; j++) acc[i][j] = 0.f;

    for (int kt = 0; kt < 33; kt++) {
        const int kb = k0 + kt * 16;
        __syncthreads();
        #pragma unroll
        for (int ii = 0; ii < 4; ii++) {
            int i = t + 256 * ii;
            int row = i >> 4, k = i & 15;
            As[k * 68 + row] = g_F[(size_t)(r0 + row) * 2112 + kb + k];
        }
        #pragma unroll
        for (int ii = 0; ii < 4; ii++) {
            int i = t + 256 * ii;
            int k = i >> 6, c = i & 63;
            Bs[k * 68 + c] = Wout[(size_t)(kb + k) * 384 + c0 + c];
        }
        __syncthreads();
        #pragma unroll
        for (int k = 0; k < 16; k++) {
            float4 a = *(const float4*)&As[k * 68 + ty * 4];
            float4 b = *(const float4*)&Bs[k * 68 + tx * 4];
            float av[4] = {a.x, a.y, a.z, a.w};
            float bw[4] = {b.x, b.y, b.z, b.w};
            #pragma unroll
            for (int i = 0; i < 4; i++)
                #pragma unroll
                for (int j = 0; j < 4; j++) acc[i][j] += av[i] * bw[j];
        }
    }
    float* Pp = g_EP + (size_t)blockIdx.z * 512 * 384;
    #pragma unroll
    for (int i = 0; i < 4; i++) {
        float4 v = {acc[i][0], acc[i][1], acc[i][2], acc[i][3]};
        *(float4*)(Pp + (size_t)(r0 + ty * 4 + i) * 384 + c0 + tx * 4) = v;
    }
}

__global__ void __launch_bounds__(256) kOutRed(float* __restrict__ out,
                                               const float* __restrict__ bout)
{
    const int e = (blockIdx.x * 256 + threadIdx.x) * 4;
    float4 acc = *(const float4*)(bout + (e % 384));
    #pragma unroll
    for (int zz = 0; zz < 4; zz++) {
        float4 p = *(const float4*)(g_EP + (size_t)zz * 512 * 384 + e);
        acc.x += p.x; acc.y += p.y; acc.z += p.z; acc.w += p.w;
    }
    *(float4*)(out + e) = acc;
}

extern "C" void kernel_launch(void* const* d_in, const int* in_sizes, int n_in,
                              void* d_out, int out_size)
{
    const float* s     = (const float*)d_in[0];
    const float* z     = (const float*)d_in[1];
    const float* trans = (const float*)d_in[2];
    const float* rot   = (const float*)d_in[3];
    // d_in[4] = mask (all true; unused)
    const float* Wq  = (const float*)d_in[5];   const float* bq  = (const float*)d_in[6];
    const float* Wk  = (const float*)d_in[7];   const float* bk  = (const float*)d_in[8];
    const float* Wv  = (const float*)d_in[9];   const float* bv  = (const float*)d_in[10];
    const float* Wqp = (const float*)d_in[11];  const float* bqp = (const float*)d_in[12];
    const float* Wkp = (const float*)d_in[13];  const float* bkp = (const float*)d_in[14];
    const float* Wvp = (const float*)d_in[15];  const float* bvp = (const float*)d_in[16];
    const float* Wb  = (const float*)d_in[17];  const float* bb  = (const float*)d_in[18];
    const float* de  = (const float*)d_in[19];
    const float* sl  = (const float*)d_in[20];
    const float* hw  = (const float*)d_in[21];
    const float* Wout = (const float*)d_in[22];
    const float* bout = (const float*)d_in[23];
    float* out = (float*)d_out;

    kProj<<<dim3(18, 8), 256>>>(s, Wq, bq, Wk, bk, Wv, bv, Wqp, bqp, Wkp, bkp, Wvp, bvp);
    pTrans<<<512, 192>>>(trans, rot);
    kT<<<dim3(16, 9, 2), 256>>>();
    kFuse<<<512, 512>>>(z, trans, rot, Wb, bb, de, sl, hw);
    kOut<<<dim3(6, 8, 4), 256>>>(Wout);
    kOutRed<<<192, 256>>>(out, bout);
}

// round 15
// speedup vs baseline: 2.4133x; 2.4133x over previous
#include <cuda_runtime.h>
#include <math.h>

__device__ float g_Q[512 * 192];
__device__ float g_K[512 * 192];
__device__ float g_V[512 * 192];
__device__ float g_QP[512 * 144];
__device__ float g_KP[512 * 144];
__device__ float g_VP[512 * 288];
__device__ float g_QG[512 * 144];
__device__ float g_KG[512 * 144];
__device__ float g_VG[512 * 288];
__device__ float g_F[512 * 2112];               // feats  [n][h*176 + f]
__device__ float g_EP[4 * 512 * 384];           // split-K partials

// ---------------- kProj: fused projection GEMM, 512 x 1152, K=384 (validated) ----------------
__device__ __forceinline__ void segSelW(int c,
    const float* Wq, const float* Wk, const float* Wv,
    const float* Wqp, const float* Wkp, const float* Wvp,
    const float*& W, int& lc, int& sn)
{
    if (c < 192)      { W = Wq;  lc = c;       sn = 192; }
    else if (c < 384) { W = Wk;  lc = c - 192; sn = 192; }
    else if (c < 576) { W = Wv;  lc = c - 384; sn = 192; }
    else if (c < 720) { W = Wqp; lc = c - 576; sn = 144; }
    else if (c < 864) { W = Wkp; lc = c - 720; sn = 144; }
    else              { W = Wvp; lc = c - 864; sn = 288; }
}

__device__ __forceinline__ void segSelO(int c,
    const float* bq, const float* bk, const float* bv,
    const float* bqp, const float* bkp, const float* bvp,
    float*& out, const float*& bia, int& lc, int& sn)
{
    if (c < 192)      { out = g_Q;  bia = bq;  lc = c;       sn = 192; }
    else if (c < 384) { out = g_K;  bia = bk;  lc = c - 192; sn = 192; }
    else if (c < 576) { out = g_V;  bia = bv;  lc = c - 384; sn = 192; }
    else if (c < 720) { out = g_QP; bia = bqp; lc = c - 576; sn = 144; }
    else if (c < 864) { out = g_KP; bia = bkp; lc = c - 720; sn = 144; }
    else              { out = g_VP; bia = bvp; lc = c - 864; sn = 288; }
}

__global__ void __launch_bounds__(256) kProj(
    const float* __restrict__ s,
    const float* __restrict__ Wq,  const float* __restrict__ bq,
    const float* __restrict__ Wk,  const float* __restrict__ bk,
    const float* __restrict__ Wv,  const float* __restrict__ bv,
    const float* __restrict__ Wqp, const float* __restrict__ bqp,
    const float* __restrict__ Wkp, const float* __restrict__ bkp,
    const float* __restrict__ Wvp, const float* __restrict__ bvp)
{
    __shared__ float As[32 * 68];
    __shared__ float Bs[32 * 68];
    const int t  = threadIdx.x;
    const int c0 = blockIdx.x * 64;
    const int r0 = blockIdx.y * 64;
    const int tx = t % 16, ty = t / 16;

    float acc[4][4];
    #pragma unroll
    for (int i = 0; i < 4; i++)
        #pragma unroll
        for (int j = 0; j < 4; j++) acc[i][j] = 0.f;

    for (int kt = 0; kt < 384; kt += 32) {
        __syncthreads();
        #pragma unroll
        for (int ii = 0; ii < 2; ii++) {
            int i4 = t + 256 * ii;
            int row = i4 >> 3, kq = i4 & 7;
            float4 a = *(const float4*)(s + (size_t)(r0 + row) * 384 + kt + kq * 4);
            As[(kq * 4 + 0) * 68 + row] = a.x;
            As[(kq * 4 + 1) * 68 + row] = a.y;
            As[(kq * 4 + 2) * 68 + row] = a.z;
            As[(kq * 4 + 3) * 68 + row] = a.w;
        }
        #pragma unroll
        for (int ii = 0; ii < 8; ii++) {
            int i = t + 256 * ii;
            int k = i >> 6, c = i & 63;
            const float* W; int lc, sn;
            segSelW(c0 + c, Wq, Wk, Wv, Wqp, Wkp, Wvp, W, lc, sn);
            Bs[k * 68 + c] = W[(size_t)(kt + k) * sn + lc];
        }
        __syncthreads();
        #pragma unroll
        for (int k = 0; k < 32; k++) {
            float4 a = *(const float4*)&As[k * 68 + ty * 4];
            float4 b = *(const float4*)&Bs[k * 68 + tx * 4];
            float av[4] = {a.x, a.y, a.z, a.w};
            float bw[4] = {b.x, b.y, b.z, b.w};
            #pragma unroll
            for (int i = 0; i < 4; i++)
                #pragma unroll
                for (int j = 0; j < 4; j++) acc[i][j] += av[i] * bw[j];
        }
    }
    float* out; const float* bia; int lc, sn;
    segSelO(c0 + tx * 4, bq, bk, bv, bqp, bkp, bvp, out, bia, lc, sn);
    float b0 = bia[lc], b1 = bia[lc + 1], b2 = bia[lc + 2], b3 = bia[lc + 3];
    #pragma unroll
    for (int i = 0; i < 4; i++) {
        int row = r0 + ty * 4 + i;
        float4 v = {acc[i][0] + b0, acc[i][1] + b1, acc[i][2] + b2, acc[i][3] + b3};
        *(float4*)(out + (size_t)row * sn + lc) = v;
    }
}

// ---------------- pTrans (validated) ----------------
__global__ void pTrans(const float* __restrict__ trans, const float* __restrict__ rot)
{
    const int n = blockIdx.x, t = threadIdx.x;   // 192 threads
    const float* R = rot + n * 9;
    const float T0 = trans[n * 3], T1 = trans[n * 3 + 1], T2 = trans[n * 3 + 2];
    const float* src; float* dst; int li;
    if (t < 48)      { src = g_QP + n * 144; dst = g_QG + n * 144; li = t; }
    else if (t < 96) { src = g_KP + n * 144; dst = g_KG + n * 144; li = t - 48; }
    else             { src = g_VP + n * 288; dst = g_VG + n * 288; li = t - 96; }
    float p0 = src[li * 3], p1 = src[li * 3 + 1], p2 = src[li * 3 + 2];
    dst[li * 3 + 0] = R[0] * p0 + R[1] * p1 + R[2] * p2 + T0;
    dst[li * 3 + 1] = R[3] * p0 + R[4] * p1 + R[5] * p2 + T1;
    dst[li * 3 + 2] = R[6] * p0 + R[7] * p1 + R[8] * p2 + T2;
}

// ---------------- kFuse2n: r10 kFuse with 2 query rows per CTA ----------------
__device__ __forceinline__ void cpAsync16(float* dst, const float* src)
{
    unsigned d = (unsigned)__cvta_generic_to_shared(dst);
    asm volatile("cp.async.cg.shared.global [%0], [%1], 16;" :: "r"(d), "l"(src));
}
#define CP_COMMIT() asm volatile("cp.async.commit_group;")
#define CP_WAIT1()  asm volatile("cp.async.wait_group 1;")
#define CP_WAIT0()  asm volatile("cp.async.wait_group 0;")

// dynamic smem layout (floats)
#define ZT_O  0        // 2 buf x 2 nn x 32 x 132 = 16896
#define LT_O  16896    // 2 nn x 416
#define Q_O   17728    // 2 x 192
#define QG_O  18112    // 2 x 144
#define WB_O  18400    // 1536
#define DE_O  19936    // 768
#define PH_O  20704    // 36
#define HW_O  20740    // 12
#define FAC_O 20752    // 2 x 12
#define RMX_O 20776    // 2 x 12
#define RSM_O 20800    // 2 x 12
#define BB_O  20824    // 12
#define F2_SMEM 20836

__global__ void __launch_bounds__(512) kFuse2n(
    const float* __restrict__ z, const float* __restrict__ trans,
    const float* __restrict__ rot,
    const float* __restrict__ Wb, const float* __restrict__ bb,
    const float* __restrict__ de, const float* __restrict__ sl,
    const float* __restrict__ hw)
{
    extern __shared__ float sm[];
    const int n0 = blockIdx.x * 2;
    const int t = threadIdx.x;
    const int wid = t >> 5, lane = t & 31;

    for (int i = t; i < 384; i += 512) sm[Q_O + i]  = g_Q[(size_t)(n0 + i / 192) * 192 + i % 192];
    for (int i = t; i < 288; i += 512) sm[QG_O + i] = g_QG[(size_t)(n0 + i / 144) * 144 + i % 144];
    for (int i = t; i < 1536; i += 512) sm[WB_O + i] = Wb[i];
    for (int i = t; i < 768; i += 512) sm[DE_O + i] = de[i];
    if (t < 12) {
        sm[HW_O + t] = hw[t];
        sm[BB_O + t] = bb[t];
        sm[RMX_O + t] = -1e30f; sm[RMX_O + 12 + t] = -1e30f;
        sm[RSM_O + t] = 0.f;    sm[RSM_O + 12 + t] = 0.f;
        float a = sl[t], b2 = sl[12 + t], c = sl[24 + t];
        float mx = fmaxf(a, fmaxf(b2, c));
        float ea = expf(a - mx), eb = expf(b2 - mx), ec = expf(c - mx);
        float inv = 1.f / (ea + eb + ec);
        sm[PH_O + t] = ea * inv; sm[PH_O + 12 + t] = eb * inv; sm[PH_O + 24 + t] = ec * inv;
    }
    float tn[2][3];
    #pragma unroll
    for (int nn = 0; nn < 2; nn++) {
        tn[nn][0] = trans[(n0 + nn) * 3];
        tn[nn][1] = trans[(n0 + nn) * 3 + 1];
        tn[nn][2] = trans[(n0 + nn) * 3 + 2];
    }

    // prefetch tile 0: 2048 float4 slots, 4 per thread
    {
        #pragma unroll
        for (int ii = 0; ii < 4; ii++) {
            int i4 = t + 512 * ii;
            int nn = i4 >> 10, mm = (i4 >> 5) & 31, c4 = i4 & 31;
            cpAsync16(sm + ZT_O + nn * 4224 + mm * 132 + c4 * 4,
                      z + ((size_t)(n0 + nn) * 512 + mm) * 128 + c4 * 4);
        }
        CP_COMMIT();
    }
    __syncthreads();

    // roles (validated r10 mapping, extended with nn loops)
    const int hb = wid * 3;             // pair head base (t<128)
    const int cq = lane * 4;            // pair cols
    float pacc[2][3][4];
    #pragma unroll
    for (int nn = 0; nn < 2; nn++)
        #pragma unroll
        for (int i = 0; i < 3; i++)
            #pragma unroll
            for (int j = 0; j < 4; j++) pacc[nn][i][j] = 0.f;
    const int js = t - 128;             // scalar lane
    const int hs = (js >= 0) ? js / 16 : 0;
    float sacc[2] = {0.f, 0.f};
    const int jp = t - 320;             // pts lane
    const int hp = (jp >= 0) ? jp / 8 : 0;
    float ap[2][3];
    #pragma unroll
    for (int nn = 0; nn < 2; nn++) { ap[nn][0] = 0.f; ap[nn][1] = 0.f; ap[nn][2] = 0.f; }
    const int Lmm = t / 12, Lh = t % 12;   // phase-L slot (t<384)

    for (int mt = 0; mt < 16; mt++) {
        const int m0 = mt * 32;
        const int cur = mt & 1;
        float* ztc = sm + ZT_O + cur * 8448;
        if (mt < 15) {
            float* ztn = sm + ZT_O + (1 - cur) * 8448;
            const int mb = m0 + 32;
            #pragma unroll
            for (int ii = 0; ii < 4; ii++) {
                int i4 = t + 512 * ii;
                int nn = i4 >> 10, mm = (i4 >> 5) & 31, c4 = i4 & 31;
                cpAsync16(ztn + nn * 4224 + mm * 132 + c4 * 4,
                          z + ((size_t)(n0 + nn) * 512 + mb + mm) * 128 + c4 * 4);
            }
            CP_COMMIT();
            CP_WAIT1();
        } else {
            CP_WAIT0();
        }
        __syncthreads();

        // ---- phase L: logits, K/KG loaded once and used for both rows ----
        if (t < 384) {
            const int m = m0 + Lmm;
            const float* kr = g_K  + (size_t)m * 192 + Lh * 16;
            const float* kg = g_KG + (size_t)m * 144 + Lh * 12;
            float krv[16], kgv[12];
            #pragma unroll
            for (int c = 0; c < 16; c++) krv[c] = kr[c];
            #pragma unroll
            for (int i = 0; i < 12; i++) kgv[i] = kg[i];
            const float tm0 = trans[m * 3], tm1 = trans[m * 3 + 1], tm2 = trans[m * 3 + 2];
            #pragma unroll
            for (int nn = 0; nn < 2; nn++) {
                float pb = sm[BB_O + Lh];
                const float* zrow = ztc + nn * 4224 + Lmm * 132;
                #pragma unroll 8
                for (int c4 = 0; c4 < 32; c4++) {
                    float4 zz = *(const float4*)(zrow + c4 * 4);
                    const float* w = &sm[WB_O + c4 * 48];
                    pb += zz.x * w[Lh] + zz.y * w[12 + Lh] + zz.z * w[24 + Lh] + zz.w * w[36 + Lh];
                }
                float dx = tn[nn][0] - tm0;
                float dy = tn[nn][1] - tm1;
                float dz = tn[nn][2] - tm2;
                float d  = sqrtf(dx * dx + dy * dy + dz * dz);
                int bin = min(max((int)ceilf(d * 2.0f) - 1, 0), 63);
                float lo = (d <= 5.0f) ? 1.f : 0.f;
                float me = (d > 5.0f && d <= 15.0f) ? 1.f : 0.f;
                float sc = 0.f;
                #pragma unroll
                for (int c = 0; c < 16; c++) sc += sm[Q_O + nn * 192 + Lh * 16 + c] * krv[c];
                float pd = 0.f;
                #pragma unroll
                for (int i = 0; i < 12; i++) {
                    float df = sm[QG_O + nn * 144 + Lh * 12 + i] - kgv[i];
                    pd += df * df;
                }
                sm[LT_O + nn * 416 + Lmm * 13 + Lh] =
                    0.25f * sc - 0.5f * pd * sm[HW_O + Lh] + pb
                    + sm[DE_O + bin * 12 + Lh]
                    + lo * sm[PH_O + Lh] + me * sm[PH_O + 12 + Lh] + sm[PH_O + 24 + Lh];
            }
        }
        __syncthreads();

        // ---- phase S: online softmax, warp per head, both rows ----
        if (wid < 12) {
            const int h = wid;
            #pragma unroll
            for (int nn = 0; nn < 2; nn++) {
                float* ltn = sm + LT_O + nn * 416;
                float l = ltn[lane * 13 + h];
                float tmax = l;
                #pragma unroll
                for (int o = 16; o; o >>= 1) tmax = fmaxf(tmax, __shfl_xor_sync(0xffffffffu, tmax, o));
                float om = sm[RMX_O + nn * 12 + h];
                float nm = fmaxf(om, tmax);
                float p = expf(l - nm);
                float tsum = p;
                #pragma unroll
                for (int o = 16; o; o >>= 1) tsum += __shfl_xor_sync(0xffffffffu, tsum, o);
                float f = expf(om - nm);
                ltn[lane * 13 + h] = p;
                if (lane == 0) {
                    sm[RMX_O + nn * 12 + h] = nm;
                    sm[RSM_O + nn * 12 + h] = sm[RSM_O + nn * 12 + h] * f + tsum;
                    sm[FAC_O + nn * 12 + h] = f;
                }
            }
        }
        __syncthreads();

        // ---- phase A: rescale + accumulate; V/VG loaded once for both rows ----
        if (t < 128) {
            #pragma unroll
            for (int nn = 0; nn < 2; nn++)
                #pragma unroll
                for (int hh = 0; hh < 3; hh++) {
                    float f = sm[FAC_O + nn * 12 + hb + hh];
                    #pragma unroll
                    for (int j = 0; j < 4; j++) pacc[nn][hh][j] *= f;
                }
            #pragma unroll 4
            for (int mm = 0; mm < 32; mm++) {
                #pragma unroll
                for (int nn = 0; nn < 2; nn++) {
                    float4 zz = *(const float4*)(ztc + nn * 4224 + mm * 132 + cq);
                    const float* pr = sm + LT_O + nn * 416 + mm * 13 + hb;
                    #pragma unroll
                    for (int hh = 0; hh < 3; hh++) {
                        float p = pr[hh];
                        pacc[nn][hh][0] += p * zz.x; pacc[nn][hh][1] += p * zz.y;
                        pacc[nn][hh][2] += p * zz.z; pacc[nn][hh][3] += p * zz.w;
                    }
                }
            }
        } else if (t < 320) {
            sacc[0] *= sm[FAC_O + hs];
            sacc[1] *= sm[FAC_O + 12 + hs];
            #pragma unroll 8
            for (int mm = 0; mm < 32; mm++) {
                float v = g_V[(size_t)(m0 + mm) * 192 + js];
                sacc[0] += sm[LT_O + mm * 13 + hs] * v;
                sacc[1] += sm[LT_O + 416 + mm * 13 + hs] * v;
            }
        } else if (t < 416) {
            #pragma unroll
            for (int nn = 0; nn < 2; nn++) {
                float f = sm[FAC_O + nn * 12 + hp];
                ap[nn][0] *= f; ap[nn][1] *= f; ap[nn][2] *= f;
            }
            #pragma unroll 8
            for (int mm = 0; mm < 32; mm++) {
                const float* vg = g_VG + (size_t)(m0 + mm) * 288 + jp * 3;
                float v0 = vg[0], v1 = vg[1], v2 = vg[2];
                float p0 = sm[LT_O + mm * 13 + hp];
                float p1 = sm[LT_O + 416 + mm * 13 + hp];
                ap[0][0] += p0 * v0; ap[0][1] += p0 * v1; ap[0][2] += p0 * v2;
                ap[1][0] += p1 * v0; ap[1][1] += p1 * v1; ap[1][2] += p1 * v2;
            }
        }
        __syncthreads();
    }

    // epilogue (validated, per row)
    if (t < 24) sm[FAC_O + t] = 1.0f / sm[RSM_O + t];
    __syncthreads();
    if (t < 128) {
        #pragma unroll
        for (int nn = 0; nn < 2; nn++)
            #pragma unroll
            for (int hh = 0; hh < 3; hh++) {
                float inv = sm[FAC_O + nn * 12 + hb + hh];
                float4 v = {pacc[nn][hh][0] * inv, pacc[nn][hh][1] * inv,
                            pacc[nn][hh][2] * inv, pacc[nn][hh][3] * inv};
                *(float4*)(g_F + (size_t)(n0 + nn) * 2112 + (hb + hh) * 176 + 48 + cq) = v;
            }
    } else if (t < 320) {
        g_F[(size_t)n0 * 2112 + hs * 176 + (js % 16)]       = sacc[0] * sm[FAC_O + hs];
        g_F[(size_t)(n0 + 1) * 2112 + hs * 176 + (js % 16)] = sacc[1] * sm[FAC_O + 12 + hs];
    } else if (t < 416) {
        const int pp = jp % 8;
        #pragma unroll
        for (int nn = 0; nn < 2; nn++) {
            float inv = sm[FAC_O + nn * 12 + hp];
            float a0 = ap[nn][0] * inv - tn[nn][0];
            float a1 = ap[nn][1] * inv - tn[nn][1];
            float a2 = ap[nn][2] * inv - tn[nn][2];
            const float* R = rot + (n0 + nn) * 9;
            float lx = R[0] * a0 + R[3] * a1 + R[6] * a2;   // R^T
            float ly = R[1] * a0 + R[4] * a1 + R[7] * a2;
            float lz = R[2] * a0 + R[5] * a1 + R[8] * a2;
            float* Fh = g_F + (size_t)(n0 + nn) * 2112 + hp * 176;
            Fh[16 + pp * 3]     = lx;
            Fh[16 + pp * 3 + 1] = ly;
            Fh[16 + pp * 3 + 2] = lz;
            Fh[40 + pp]         = sqrtf(lx * lx + ly * ly + lz * lz);
        }
    }
}

// ---------------- kOut: tiled split-K GEMM 512x384, K=2112 (validated, splitK 4) ----------------
__global__ void __launch_bounds__(256) kOut(const float* __restrict__ Wout)
{
    __shared__ float As[16 * 68];
    __shared__ float Bs[16 * 68];
    const int t  = threadIdx.x;
    const int c0 = blockIdx.x * 64;
    const int r0 = blockIdx.y * 64;
    const int k0 = blockIdx.z * 528;
    const int tx = t % 16, ty = t / 16;
    float acc[4][4];
    #pragma unroll
    for (int i = 0; i < 4; i++)
        #pragma unroll
        for (int j = 0; j < 4; j++) acc[i][j] = 0.f;

    for (int kt = 0; kt < 33; kt++) {
        const int kb = k0 + kt * 16;
        __syncthreads();
        #pragma unroll
        for (int ii = 0; ii < 4; ii++) {
            int i = t + 256 * ii;
            int row = i >> 4, k = i & 15;
            As[k * 68 + row] = g_F[(size_t)(r0 + row) * 2112 + kb + k];
        }
        #pragma unroll
        for (int ii = 0; ii < 4; ii++) {
            int i = t + 256 * ii;
            int k = i >> 6, c = i & 63;
            Bs[k * 68 + c] = Wout[(size_t)(kb + k) * 384 + c0 + c];
        }
        __syncthreads();
        #pragma unroll
        for (int k = 0; k < 16; k++) {
            float4 a = *(const float4*)&As[k * 68 + ty * 4];
            float4 b = *(const float4*)&Bs[k * 68 + tx * 4];
            float av[4] = {a.x, a.y, a.z, a.w};
            float bw[4] = {b.x, b.y, b.z, b.w};
            #pragma unroll
            for (int i = 0; i < 4; i++)
                #pragma unroll
                for (int j = 0; j < 4; j++) acc[i][j] += av[i] * bw[j];
        }
    }
    float* Pp = g_EP + (size_t)blockIdx.z * 512 * 384;
    #pragma unroll
    for (int i = 0; i < 4; i++) {
        float4 v = {acc[i][0], acc[i][1], acc[i][2], acc[i][3]};
        *(float4*)(Pp + (size_t)(r0 + ty * 4 + i) * 384 + c0 + tx * 4) = v;
    }
}

__global__ void __launch_bounds__(256) kOutRed(float* __restrict__ out,
                                               const float* __restrict__ bout)
{
    const int e = (blockIdx.x * 256 + threadIdx.x) * 4;
    float4 acc = *(const float4*)(bout + (e % 384));
    #pragma unroll
    for (int zz = 0; zz < 4; zz++) {
        float4 p = *(const float4*)(g_EP + (size_t)zz * 512 * 384 + e);
        acc.x += p.x; acc.y += p.y; acc.z += p.z; acc.w += p.w;
    }
    *(float4*)(out + e) = acc;
}

extern "C" void kernel_launch(void* const* d_in, const int* in_sizes, int n_in,
                              void* d_out, int out_size)
{
    const float* s     = (const float*)d_in[0];
    const float* z     = (const float*)d_in[1];
    const float* trans = (const float*)d_in[2];
    const float* rot   = (const float*)d_in[3];
    // d_in[4] = mask (all true; unused)
    const float* Wq  = (const float*)d_in[5];   const float* bq  = (const float*)d_in[6];
    const float* Wk  = (const float*)d_in[7];   const float* bk  = (const float*)d_in[8];
    const float* Wv  = (const float*)d_in[9];   const float* bv  = (const float*)d_in[10];
    const float* Wqp = (const float*)d_in[11];  const float* bqp = (const float*)d_in[12];
    const float* Wkp = (const float*)d_in[13];  const float* bkp = (const float*)d_in[14];
    const float* Wvp = (const float*)d_in[15];  const float* bvp = (const float*)d_in[16];
    const float* Wb  = (const float*)d_in[17];  const float* bb  = (const float*)d_in[18];
    const float* de  = (const float*)d_in[19];
    const float* sl  = (const float*)d_in[20];
    const float* hw  = (const float*)d_in[21];
    const float* Wout = (const float*)d_in[22];
    const float* bout = (const float*)d_in[23];
    float* out = (float*)d_out;

    cudaFuncSetAttribute(kFuse2n, cudaFuncAttributeMaxDynamicSharedMemorySize,
                         F2_SMEM * 4);

    kProj<<<dim3(18, 8), 256>>>(s, Wq, bq, Wk, bk, Wv, bv, Wqp, bqp, Wkp, bkp, Wvp, bvp);
    pTrans<<<512, 192>>>(trans, rot);
    kFuse2n<<<256, 512, F2_SMEM * 4>>>(z, trans, rot, Wb, bb, de, sl, hw);
    kOut<<<dim3(6, 8, 4), 256>>>(Wout);
    kOutRed<<<192, 256>>>(out, bout);
}

// round 16
// speedup vs baseline: 3.1322x; 1.2979x over previous
#include <cuda_runtime.h>
#include <math.h>

__device__ float g_Q[512 * 192];
__device__ float g_K[512 * 192];
__device__ float g_V[512 * 192];
__device__ float g_QP[512 * 144];
__device__ float g_KP[512 * 144];
__device__ float g_VP[512 * 288];
__device__ float g_QG[512 * 144];
__device__ float g_KG[512 * 144];
__device__ float g_VG[512 * 288];
__device__ float g_KT[192 * 512];               // K transposed  [hc][m]
__device__ float g_KGT[144 * 512];              // KG transposed [hi][m]
__device__ float g_F[512 * 2112];               // feats  [n][h*176 + f]
__device__ float g_EP[4 * 512 * 384];           // split-K partials

// ---------------- kProj: fused projection GEMM, 512 x 1152, K=384 (validated) ----------------
__device__ __forceinline__ void segSelW(int c,
    const float* Wq, const float* Wk, const float* Wv,
    const float* Wqp, const float* Wkp, const float* Wvp,
    const float*& W, int& lc, int& sn)
{
    if (c < 192)      { W = Wq;  lc = c;       sn = 192; }
    else if (c < 384) { W = Wk;  lc = c - 192; sn = 192; }
    else if (c < 576) { W = Wv;  lc = c - 384; sn = 192; }
    else if (c < 720) { W = Wqp; lc = c - 576; sn = 144; }
    else if (c < 864) { W = Wkp; lc = c - 720; sn = 144; }
    else              { W = Wvp; lc = c - 864; sn = 288; }
}

__device__ __forceinline__ void segSelO(int c,
    const float* bq, const float* bk, const float* bv,
    const float* bqp, const float* bkp, const float* bvp,
    float*& out, const float*& bia, int& lc, int& sn)
{
    if (c < 192)      { out = g_Q;  bia = bq;  lc = c;       sn = 192; }
    else if (c < 384) { out = g_K;  bia = bk;  lc = c - 192; sn = 192; }
    else if (c < 576) { out = g_V;  bia = bv;  lc = c - 384; sn = 192; }
    else if (c < 720) { out = g_QP; bia = bqp; lc = c - 576; sn = 144; }
    else if (c < 864) { out = g_KP; bia = bkp; lc = c - 720; sn = 144; }
    else              { out = g_VP; bia = bvp; lc = c - 864; sn = 288; }
}

__global__ void __launch_bounds__(256) kProj(
    const float* __restrict__ s,
    const float* __restrict__ Wq,  const float* __restrict__ bq,
    const float* __restrict__ Wk,  const float* __restrict__ bk,
    const float* __restrict__ Wv,  const float* __restrict__ bv,
    const float* __restrict__ Wqp, const float* __restrict__ bqp,
    const float* __restrict__ Wkp, const float* __restrict__ bkp,
    const float* __restrict__ Wvp, const float* __restrict__ bvp)
{
    __shared__ float As[32 * 68];
    __shared__ float Bs[32 * 68];
    const int t  = threadIdx.x;
    const int c0 = blockIdx.x * 64;
    const int r0 = blockIdx.y * 64;
    const int tx = t % 16, ty = t / 16;

    float acc[4][4];
    #pragma unroll
    for (int i = 0; i < 4; i++)
        #pragma unroll
        for (int j = 0; j < 4; j++) acc[i][j] = 0.f;

    for (int kt = 0; kt < 384; kt += 32) {
        __syncthreads();
        #pragma unroll
        for (int ii = 0; ii < 2; ii++) {
            int i4 = t + 256 * ii;
            int row = i4 >> 3, kq = i4 & 7;
            float4 a = *(const float4*)(s + (size_t)(r0 + row) * 384 + kt + kq * 4);
            As[(kq * 4 + 0) * 68 + row] = a.x;
            As[(kq * 4 + 1) * 68 + row] = a.y;
            As[(kq * 4 + 2) * 68 + row] = a.z;
            As[(kq * 4 + 3) * 68 + row] = a.w;
        }
        #pragma unroll
        for (int ii = 0; ii < 8; ii++) {
            int i = t + 256 * ii;
            int k = i >> 6, c = i & 63;
            const float* W; int lc, sn;
            segSelW(c0 + c, Wq, Wk, Wv, Wqp, Wkp, Wvp, W, lc, sn);
            Bs[k * 68 + c] = W[(size_t)(kt + k) * sn + lc];
        }
        __syncthreads();
        #pragma unroll
        for (int k = 0; k < 32; k++) {
            float4 a = *(const float4*)&As[k * 68 + ty * 4];
            float4 b = *(const float4*)&Bs[k * 68 + tx * 4];
            float av[4] = {a.x, a.y, a.z, a.w};
            float bw[4] = {b.x, b.y, b.z, b.w};
            #pragma unroll
            for (int i = 0; i < 4; i++)
                #pragma unroll
                for (int j = 0; j < 4; j++) acc[i][j] += av[i] * bw[j];
        }
    }
    float* out; const float* bia; int lc, sn;
    segSelO(c0 + tx * 4, bq, bk, bv, bqp, bkp, bvp, out, bia, lc, sn);
    float b0 = bia[lc], b1 = bia[lc + 1], b2 = bia[lc + 2], b3 = bia[lc + 3];
    #pragma unroll
    for (int i = 0; i < 4; i++) {
        int row = r0 + ty * 4 + i;
        float4 v = {acc[i][0] + b0, acc[i][1] + b1, acc[i][2] + b2, acc[i][3] + b3};
        *(float4*)(out + (size_t)row * sn + lc) = v;
    }
}

// ---------------- pTrans (validated) ----------------
__global__ void pTrans(const float* __restrict__ trans, const float* __restrict__ rot)
{
    const int n = blockIdx.x, t = threadIdx.x;   // 192 threads
    const float* R = rot + n * 9;
    const float T0 = trans[n * 3], T1 = trans[n * 3 + 1], T2 = trans[n * 3 + 2];
    const float* src; float* dst; int li;
    if (t < 48)      { src = g_QP + n * 144; dst = g_QG + n * 144; li = t; }
    else if (t < 96) { src = g_KP + n * 144; dst = g_KG + n * 144; li = t - 48; }
    else             { src = g_VP + n * 288; dst = g_VG + n * 288; li = t - 96; }
    float p0 = src[li * 3], p1 = src[li * 3 + 1], p2 = src[li * 3 + 2];
    dst[li * 3 + 0] = R[0] * p0 + R[1] * p1 + R[2] * p2 + T0;
    dst[li * 3 + 1] = R[3] * p0 + R[4] * p1 + R[5] * p2 + T1;
    dst[li * 3 + 2] = R[6] * p0 + R[7] * p1 + R[8] * p2 + T2;
}

// ---------------- kT2: transpose K (512x192) and KG (512x144) ----------------
__global__ void __launch_bounds__(256) kT2()
{
    __shared__ float tile[32][33];
    const int which = blockIdx.z;
    const float* src = which ? g_KG : g_K;
    float* dst = which ? g_KGT : g_KT;
    const int C = which ? 144 : 192;
    const int m0 = blockIdx.x * 32;
    const int c0 = blockIdx.y * 32;
    if (c0 >= C) return;
    const int tx = threadIdx.x & 31, ty = threadIdx.x >> 5;   // 32 x 8
    #pragma unroll
    for (int i = ty; i < 32; i += 8)
        if (c0 + tx < C)
            tile[i][tx] = src[(size_t)(m0 + i) * C + c0 + tx];
    __syncthreads();
    #pragma unroll
    for (int i = ty; i < 32; i += 8)
        if (c0 + i < C)
            dst[(size_t)(c0 + i) * 512 + m0 + tx] = tile[tx][i];
}

// ---------------- kFuse3: 2 rows/CTA, fused L+S (warp=head), validated phase A ----------------
__device__ __forceinline__ void cpAsync16(float* dst, const float* src)
{
    unsigned d = (unsigned)__cvta_generic_to_shared(dst);
    asm volatile("cp.async.cg.shared.global [%0], [%1], 16;" :: "r"(d), "l"(src));
}
#define CP_COMMIT() asm volatile("cp.async.commit_group;")
#define CP_WAIT1()  asm volatile("cp.async.wait_group 1;")
#define CP_WAIT0()  asm volatile("cp.async.wait_group 0;")

// dynamic smem layout (floats)
#define ZT_O  0        // 2 buf x 2 nn x 32 x 132 = 16896
#define LT_O  16896    // 2 nn x 416
#define Q_O   17728    // 2 x 192
#define QG_O  18112    // 2 x 144
#define WB_O  18400    // 1536
#define DE_O  19936    // 768
#define PH_O  20704    // 36
#define HW_O  20740    // 12
#define FAC_O 20752    // 2 x 12
#define RMX_O 20776    // 2 x 12
#define RSM_O 20800    // 2 x 12
#define BB_O  20824    // 12
#define TR_O  20836    // 1536 (trans staged)
#define F3_SMEM 22372

__global__ void __launch_bounds__(512, 2) kFuse3(
    const float* __restrict__ z, const float* __restrict__ trans,
    const float* __restrict__ rot,
    const float* __restrict__ Wb, const float* __restrict__ bb,
    const float* __restrict__ de, const float* __restrict__ sl,
    const float* __restrict__ hw)
{
    extern __shared__ float sm[];
    const int n0 = blockIdx.x * 2;
    const int t = threadIdx.x;
    const int wid = t >> 5, lane = t & 31;

    for (int i = t; i < 384; i += 512) sm[Q_O + i]  = g_Q[(size_t)(n0 + i / 192) * 192 + i % 192];
    for (int i = t; i < 288; i += 512) sm[QG_O + i] = g_QG[(size_t)(n0 + i / 144) * 144 + i % 144];
    for (int i = t; i < 1536; i += 512) sm[WB_O + i] = Wb[i];
    for (int i = t; i < 768; i += 512) sm[DE_O + i] = de[i];
    for (int i = t; i < 1536; i += 512) sm[TR_O + i] = trans[i];
    if (t < 12) {
        sm[HW_O + t] = hw[t];
        sm[BB_O + t] = bb[t];
        sm[RMX_O + t] = -1e30f; sm[RMX_O + 12 + t] = -1e30f;
        sm[RSM_O + t] = 0.f;    sm[RSM_O + 12 + t] = 0.f;
        float a = sl[t], b2 = sl[12 + t], c = sl[24 + t];
        float mx = fmaxf(a, fmaxf(b2, c));
        float ea = expf(a - mx), eb = expf(b2 - mx), ec = expf(c - mx);
        float inv = 1.f / (ea + eb + ec);
        sm[PH_O + t] = ea * inv; sm[PH_O + 12 + t] = eb * inv; sm[PH_O + 24 + t] = ec * inv;
    }
    float tn[2][3];
    #pragma unroll
    for (int nn = 0; nn < 2; nn++) {
        tn[nn][0] = trans[(n0 + nn) * 3];
        tn[nn][1] = trans[(n0 + nn) * 3 + 1];
        tn[nn][2] = trans[(n0 + nn) * 3 + 2];
    }

    // prefetch tile 0: 2048 float4 slots, 4 per thread
    {
        #pragma unroll
        for (int ii = 0; ii < 4; ii++) {
            int i4 = t + 512 * ii;
            int nn = i4 >> 10, mm = (i4 >> 5) & 31, c4 = i4 & 31;
            cpAsync16(sm + ZT_O + nn * 4224 + mm * 132 + c4 * 4,
                      z + ((size_t)(n0 + nn) * 512 + mm) * 128 + c4 * 4);
        }
        CP_COMMIT();
    }
    __syncthreads();

    // roles for phase A (validated r14 mapping)
    const int hb = wid * 3;             // pair head base (t<128)
    const int cq = lane * 4;            // pair cols
    float pacc[2][3][4];
    #pragma unroll
    for (int nn = 0; nn < 2; nn++)
        #pragma unroll
        for (int i = 0; i < 3; i++)
            #pragma unroll
            for (int j = 0; j < 4; j++) pacc[nn][i][j] = 0.f;
    const int js = t - 128;             // scalar lane
    const int hs = (js >= 0) ? js / 16 : 0;
    float sacc[2] = {0.f, 0.f};
    const int jp = t - 320;             // pts lane
    const int hp = (jp >= 0) ? jp / 8 : 0;
    float ap[2][3];
    #pragma unroll
    for (int nn = 0; nn < 2; nn++) { ap[nn][0] = 0.f; ap[nn][1] = 0.f; ap[nn][2] = 0.f; }

    for (int mt = 0; mt < 16; mt++) {
        const int m0 = mt * 32;
        const int cur = mt & 1;
        float* ztc = sm + ZT_O + cur * 8448;
        if (mt < 15) {
            float* ztn = sm + ZT_O + (1 - cur) * 8448;
            const int mb = m0 + 32;
            #pragma unroll
            for (int ii = 0; ii < 4; ii++) {
                int i4 = t + 512 * ii;
                int nn = i4 >> 10, mm = (i4 >> 5) & 31, c4 = i4 & 31;
                cpAsync16(ztn + nn * 4224 + mm * 132 + c4 * 4,
                          z + ((size_t)(n0 + nn) * 512 + mb + mm) * 128 + c4 * 4);
            }
            CP_COMMIT();
            CP_WAIT1();
        } else {
            CP_WAIT0();
        }
        __syncthreads();

        // ---- fused phase L+S: warp = head, lane = m (validated formulas inline) ----
        if (wid < 12) {
            const int h = wid;
            const int m = m0 + lane;
            float krv[16], kgv[12];
            #pragma unroll
            for (int c = 0; c < 16; c++) krv[c] = g_KT[(size_t)(h * 16 + c) * 512 + m];
            #pragma unroll
            for (int i = 0; i < 12; i++) kgv[i] = g_KGT[(size_t)(h * 12 + i) * 512 + m];
            const float tm0 = sm[TR_O + m * 3], tm1 = sm[TR_O + m * 3 + 1], tm2 = sm[TR_O + m * 3 + 2];
            // merged z.Wb for both rows (w read once)
            float pb0 = sm[BB_O + h], pb1 = pb0;
            const float* zr0 = ztc + lane * 132;
            const float* zr1 = ztc + 4224 + lane * 132;
            #pragma unroll 8
            for (int c4 = 0; c4 < 32; c4++) {
                const float* w = &sm[WB_O + c4 * 48];
                float w0 = w[h], w1 = w[12 + h], w2 = w[24 + h], w3 = w[36 + h];
                float4 a = *(const float4*)(zr0 + c4 * 4);
                float4 b = *(const float4*)(zr1 + c4 * 4);
                pb0 += a.x * w0 + a.y * w1 + a.z * w2 + a.w * w3;
                pb1 += b.x * w0 + b.y * w1 + b.z * w2 + b.w * w3;
            }
            #pragma unroll
            for (int nn = 0; nn < 2; nn++) {
                float dx = tn[nn][0] - tm0;
                float dy = tn[nn][1] - tm1;
                float dz = tn[nn][2] - tm2;
                float d  = sqrtf(dx * dx + dy * dy + dz * dz);
                int bin = min(max((int)ceilf(d * 2.0f) - 1, 0), 63);
                float lo = (d <= 5.0f) ? 1.f : 0.f;
                float me = (d > 5.0f && d <= 15.0f) ? 1.f : 0.f;
                float sc = 0.f;
                #pragma unroll
                for (int c = 0; c < 16; c++) sc += sm[Q_O + nn * 192 + h * 16 + c] * krv[c];
                float pd = 0.f;
                #pragma unroll
                for (int i = 0; i < 12; i++) {
                    float df = sm[QG_O + nn * 144 + h * 12 + i] - kgv[i];
                    pd += df * df;
                }
                float l = 0.25f * sc - 0.5f * pd * sm[HW_O + h] + (nn ? pb1 : pb0)
                        + sm[DE_O + bin * 12 + h]
                        + lo * sm[PH_O + h] + me * sm[PH_O + 12 + h] + sm[PH_O + 24 + h];
                // inline online-softmax update (same math as validated phase S)
                float tmax = l;
                #pragma unroll
                for (int o = 16; o; o >>= 1) tmax = fmaxf(tmax, __shfl_xor_sync(0xffffffffu, tmax, o));
                float om = sm[RMX_O + nn * 12 + h];
                float nm = fmaxf(om, tmax);
                float p = expf(l - nm);
                float tsum = p;
                #pragma unroll
                for (int o = 16; o; o >>= 1) tsum += __shfl_xor_sync(0xffffffffu, tsum, o);
                sm[LT_O + nn * 416 + lane * 13 + h] = p;
                if (lane == 0) {
                    float f = expf(om - nm);
                    sm[RMX_O + nn * 12 + h] = nm;
                    sm[RSM_O + nn * 12 + h] = sm[RSM_O + nn * 12 + h] * f + tsum;
                    sm[FAC_O + nn * 12 + h] = f;
                }
            }
        }
        __syncthreads();

        // ---- phase A: rescale + accumulate (validated r14, unchanged) ----
        if (t < 128) {
            #pragma unroll
            for (int nn = 0; nn < 2; nn++)
                #pragma unroll
                for (int hh = 0; hh < 3; hh++) {
                    float f = sm[FAC_O + nn * 12 + hb + hh];
                    #pragma unroll
                    for (int j = 0; j < 4; j++) pacc[nn][hh][j] *= f;
                }
            #pragma unroll 4
            for (int mm = 0; mm < 32; mm++) {
                #pragma unroll
                for (int nn = 0; nn < 2; nn++) {
                    float4 zz = *(const float4*)(ztc + nn * 4224 + mm * 132 + cq);
                    const float* pr = sm + LT_O + nn * 416 + mm * 13 + hb;
                    #pragma unroll
                    for (int hh = 0; hh < 3; hh++) {
                        float p = pr[hh];
                        pacc[nn][hh][0] += p * zz.x; pacc[nn][hh][1] += p * zz.y;
                        pacc[nn][hh][2] += p * zz.z; pacc[nn][hh][3] += p * zz.w;
                    }
                }
            }
        } else if (t < 320) {
            sacc[0] *= sm[FAC_O + hs];
            sacc[1] *= sm[FAC_O + 12 + hs];
            #pragma unroll 8
            for (int mm = 0; mm < 32; mm++) {
                float v = g_V[(size_t)(m0 + mm) * 192 + js];
                sacc[0] += sm[LT_O + mm * 13 + hs] * v;
                sacc[1] += sm[LT_O + 416 + mm * 13 + hs] * v;
            }
        } else if (t < 416) {
            #pragma unroll
            for (int nn = 0; nn < 2; nn++) {
                float f = sm[FAC_O + nn * 12 + hp];
                ap[nn][0] *= f; ap[nn][1] *= f; ap[nn][2] *= f;
            }
            #pragma unroll 8
            for (int mm = 0; mm < 32; mm++) {
                const float* vg = g_VG + (size_t)(m0 + mm) * 288 + jp * 3;
                float v0 = vg[0], v1 = vg[1], v2 = vg[2];
                float p0 = sm[LT_O + mm * 13 + hp];
                float p1 = sm[LT_O + 416 + mm * 13 + hp];
                ap[0][0] += p0 * v0; ap[0][1] += p0 * v1; ap[0][2] += p0 * v2;
                ap[1][0] += p1 * v0; ap[1][1] += p1 * v1; ap[1][2] += p1 * v2;
            }
        }
        __syncthreads();
    }

    // epilogue (validated, per row)
    if (t < 24) sm[FAC_O + t] = 1.0f / sm[RSM_O + t];
    __syncthreads();
    if (t < 128) {
        #pragma unroll
        for (int nn = 0; nn < 2; nn++)
            #pragma unroll
            for (int hh = 0; hh < 3; hh++) {
                float inv = sm[FAC_O + nn * 12 + hb + hh];
                float4 v = {pacc[nn][hh][0] * inv, pacc[nn][hh][1] * inv,
                            pacc[nn][hh][2] * inv, pacc[nn][hh][3] * inv};
                *(float4*)(g_F + (size_t)(n0 + nn) * 2112 + (hb + hh) * 176 + 48 + cq) = v;
            }
    } else if (t < 320) {
        g_F[(size_t)n0 * 2112 + hs * 176 + (js % 16)]       = sacc[0] * sm[FAC_O + hs];
        g_F[(size_t)(n0 + 1) * 2112 + hs * 176 + (js % 16)] = sacc[1] * sm[FAC_O + 12 + hs];
    } else if (t < 416) {
        const int pp = jp % 8;
        #pragma unroll
        for (int nn = 0; nn < 2; nn++) {
            float inv = sm[FAC_O + nn * 12 + hp];
            float a0 = ap[nn][0] * inv - tn[nn][0];
            float a1 = ap[nn][1] * inv - tn[nn][1];
            float a2 = ap[nn][2] * inv - tn[nn][2];
            const float* R = rot + (n0 + nn) * 9;
            float lx = R[0] * a0 + R[3] * a1 + R[6] * a2;   // R^T
            float ly = R[1] * a0 + R[4] * a1 + R[7] * a2;
            float lz = R[2] * a0 + R[5] * a1 + R[8] * a2;
            float* Fh = g_F + (size_t)(n0 + nn) * 2112 + hp * 176;
            Fh[16 + pp * 3]     = lx;
            Fh[16 + pp * 3 + 1] = ly;
            Fh[16 + pp * 3 + 2] = lz;
            Fh[40 + pp]         = sqrtf(lx * lx + ly * ly + lz * lz);
        }
    }
}

// ---------------- kOut: tiled split-K GEMM 512x384, K=2112 (validated, splitK 4) ----------------
__global__ void __launch_bounds__(256) kOut(const float* __restrict__ Wout)
{
    __shared__ float As[16 * 68];
    __shared__ float Bs[16 * 68];
    const int t  = threadIdx.x;
    const int c0 = blockIdx.x * 64;
    const int r0 = blockIdx.y * 64;
    const int k0 = blockIdx.z * 528;
    const int tx = t % 16, ty = t / 16;
    float acc[4][4];
    #pragma unroll
    for (int i = 0; i < 4; i++)
        #pragma unroll
        for (int j = 0; j < 4; j++) acc[i][j] = 0.f;

    for (int kt = 0; kt < 33; kt++) {
        const int kb = k0 + kt * 16;
        __syncthreads();
        #pragma unroll
        for (int ii = 0; ii < 4; ii++) {
            int i = t + 256 * ii;
            int row = i >> 4, k = i & 15;
            As[k * 68 + row] = g_F[(size_t)(r0 + row) * 2112 + kb + k];
        }
        #pragma unroll
        for (int ii = 0; ii < 4; ii++) {
            int i = t + 256 * ii;
            int k = i >> 6, c = i & 63;
            Bs[k * 68 + c] = Wout[(size_t)(kb + k) * 384 + c0 + c];
        }
        __syncthreads();
        #pragma unroll
        for (int k = 0; k < 16; k++) {
            float4 a = *(const float4*)&As[k * 68 + ty * 4];
            float4 b = *(const float4*)&Bs[k * 68 + tx * 4];
            float av[4] = {a.x, a.y, a.z, a.w};
            float bw[4] = {b.x, b.y, b.z, b.w};
            #pragma unroll
            for (int i = 0; i < 4; i++)
                #pragma unroll
                for (int j = 0; j < 4; j++) acc[i][j] += av[i] * bw[j];
        }
    }
    float* Pp = g_EP + (size_t)blockIdx.z * 512 * 384;
    #pragma unroll
    for (int i = 0; i < 4; i++) {
        float4 v = {acc[i][0], acc[i][1], acc[i][2], acc[i][3]};
        *(float4*)(Pp + (size_t)(r0 + ty * 4 + i) * 384 + c0 + tx * 4) = v;
    }
}

__global__ void __launch_bounds__(256) kOutRed(float* __restrict__ out,
                                               const float* __restrict__ bout)
{
    const int e = (blockIdx.x * 256 + threadIdx.x) * 4;
    float4 acc = *(const float4*)(bout + (e % 384));
    #pragma unroll
    for (int zz = 0; zz < 4; zz++) {
        float4 p = *(const float4*)(g_EP + (size_t)zz * 512 * 384 + e);
        acc.x += p.x; acc.y += p.y; acc.z += p.z; acc.w += p.w;
    }
    *(float4*)(out + e) = acc;
}

extern "C" void kernel_launch(void* const* d_in, const int* in_sizes, int n_in,
                              void* d_out, int out_size)
{
    const float* s     = (const float*)d_in[0];
    const float* z     = (const float*)d_in[1];
    const float* trans = (const float*)d_in[2];
    const float* rot   = (const float*)d_in[3];
    // d_in[4] = mask (all true; unused)
    const float* Wq  = (const float*)d_in[5];   const float* bq  = (const float*)d_in[6];
    const float* Wk  = (const float*)d_in[7];   const float* bk  = (const float*)d_in[8];
    const float* Wv  = (const float*)d_in[9];   const float* bv  = (const float*)d_in[10];
    const float* Wqp = (const float*)d_in[11];  const float* bqp = (const float*)d_in[12];
    const float* Wkp = (const float*)d_in[13];  const float* bkp = (const float*)d_in[14];
    const float* Wvp = (const float*)d_in[15];  const float* bvp = (const float*)d_in[16];
    const float* Wb  = (const float*)d_in[17];  const float* bb  = (const float*)d_in[18];
    const float* de  = (const float*)d_in[19];
    const float* sl  = (const float*)d_in[20];
    const float* hw  = (const float*)d_in[21];
    const float* Wout = (const float*)d_in[22];
    const float* bout = (const float*)d_in[23];
    float* out = (float*)d_out;

    cudaFuncSetAttribute(kFuse3, cudaFuncAttributeMaxDynamicSharedMemorySize,
                         F3_SMEM * 4);

    kProj<<<dim3(18, 8), 256>>>(s, Wq, bq, Wk, bk, Wv, bv, Wqp, bqp, Wkp, bkp, Wvp, bvp);
    pTrans<<<512, 192>>>(trans, rot);
    kT2<<<dim3(16, 6, 2), 256>>>();
    kFuse3<<<256, 512, F3_SMEM * 4>>>(z, trans, rot, Wb, bb, de, sl, hw);
    kOut<<<dim3(6, 8, 4), 256>>>(Wout);
    kOutRed<<<192, 256>>>(out, bout);
}

// round 17
// speedup vs baseline: 3.5848x; 1.1445x over previous
#include <cuda_runtime.h>
#include <math.h>

__device__ float g_Q[512 * 192];
__device__ float g_K[512 * 192];
__device__ float g_V[512 * 192];
__device__ float g_QP[512 * 144];
__device__ float g_KP[512 * 144];
__device__ float g_VP[512 * 288];
__device__ float g_QG[512 * 144];
__device__ float g_KG[512 * 144];
__device__ float g_VG[512 * 288];
__device__ float g_KT[192 * 512];               // K transposed  [hc][m]
__device__ float g_KGT[144 * 512];              // KG transposed [hi][m]
__device__ float g_F[512 * 2112];               // feats  [n][h*176 + f]
__device__ float g_EP[12 * 512 * 384];          // split-K partials

// ---------------- kProj: fused projection GEMM, 512 x 1152, K=384 (validated) ----------------
__device__ __forceinline__ void segSelW(int c,
    const float* Wq, const float* Wk, const float* Wv,
    const float* Wqp, const float* Wkp, const float* Wvp,
    const float*& W, int& lc, int& sn)
{
    if (c < 192)      { W = Wq;  lc = c;       sn = 192; }
    else if (c < 384) { W = Wk;  lc = c - 192; sn = 192; }
    else if (c < 576) { W = Wv;  lc = c - 384; sn = 192; }
    else if (c < 720) { W = Wqp; lc = c - 576; sn = 144; }
    else if (c < 864) { W = Wkp; lc = c - 720; sn = 144; }
    else              { W = Wvp; lc = c - 864; sn = 288; }
}

__device__ __forceinline__ void segSelO(int c,
    const float* bq, const float* bk, const float* bv,
    const float* bqp, const float* bkp, const float* bvp,
    float*& out, const float*& bia, int& lc, int& sn)
{
    if (c < 192)      { out = g_Q;  bia = bq;  lc = c;       sn = 192; }
    else if (c < 384) { out = g_K;  bia = bk;  lc = c - 192; sn = 192; }
    else if (c < 576) { out = g_V;  bia = bv;  lc = c - 384; sn = 192; }
    else if (c < 720) { out = g_QP; bia = bqp; lc = c - 576; sn = 144; }
    else if (c < 864) { out = g_KP; bia = bkp; lc = c - 720; sn = 144; }
    else              { out = g_VP; bia = bvp; lc = c - 864; sn = 288; }
}

__global__ void __launch_bounds__(256) kProj(
    const float* __restrict__ s,
    const float* __restrict__ Wq,  const float* __restrict__ bq,
    const float* __restrict__ Wk,  const float* __restrict__ bk,
    const float* __restrict__ Wv,  const float* __restrict__ bv,
    const float* __restrict__ Wqp, const float* __restrict__ bqp,
    const float* __restrict__ Wkp, const float* __restrict__ bkp,
    const float* __restrict__ Wvp, const float* __restrict__ bvp)
{
    __shared__ float As[32 * 68];
    __shared__ float Bs[32 * 68];
    const int t  = threadIdx.x;
    const int c0 = blockIdx.x * 64;
    const int r0 = blockIdx.y * 64;
    const int tx = t % 16, ty = t / 16;

    float acc[4][4];
    #pragma unroll
    for (int i = 0; i < 4; i++)
        #pragma unroll
        for (int j = 0; j < 4; j++) acc[i][j] = 0.f;

    for (int kt = 0; kt < 384; kt += 32) {
        __syncthreads();
        #pragma unroll
        for (int ii = 0; ii < 2; ii++) {
            int i4 = t + 256 * ii;
            int row = i4 >> 3, kq = i4 & 7;
            float4 a = *(const float4*)(s + (size_t)(r0 + row) * 384 + kt + kq * 4);
            As[(kq * 4 + 0) * 68 + row] = a.x;
            As[(kq * 4 + 1) * 68 + row] = a.y;
            As[(kq * 4 + 2) * 68 + row] = a.z;
            As[(kq * 4 + 3) * 68 + row] = a.w;
        }
        #pragma unroll
        for (int ii = 0; ii < 8; ii++) {
            int i = t + 256 * ii;
            int k = i >> 6, c = i & 63;
            const float* W; int lc, sn;
            segSelW(c0 + c, Wq, Wk, Wv, Wqp, Wkp, Wvp, W, lc, sn);
            Bs[k * 68 + c] = W[(size_t)(kt + k) * sn + lc];
        }
        __syncthreads();
        #pragma unroll
        for (int k = 0; k < 32; k++) {
            float4 a = *(const float4*)&As[k * 68 + ty * 4];
            float4 b = *(const float4*)&Bs[k * 68 + tx * 4];
            float av[4] = {a.x, a.y, a.z, a.w};
            float bw[4] = {b.x, b.y, b.z, b.w};
            #pragma unroll
            for (int i = 0; i < 4; i++)
                #pragma unroll
                for (int j = 0; j < 4; j++) acc[i][j] += av[i] * bw[j];
        }
    }
    float* out; const float* bia; int lc, sn;
    segSelO(c0 + tx * 4, bq, bk, bv, bqp, bkp, bvp, out, bia, lc, sn);
    float b0 = bia[lc], b1 = bia[lc + 1], b2 = bia[lc + 2], b3 = bia[lc + 3];
    #pragma unroll
    for (int i = 0; i < 4; i++) {
        int row = r0 + ty * 4 + i;
        float4 v = {acc[i][0] + b0, acc[i][1] + b1, acc[i][2] + b2, acc[i][3] + b3};
        *(float4*)(out + (size_t)row * sn + lc) = v;
    }
}

// ---------------- pTrans (validated) ----------------
__global__ void pTrans(const float* __restrict__ trans, const float* __restrict__ rot)
{
    const int n = blockIdx.x, t = threadIdx.x;   // 192 threads
    const float* R = rot + n * 9;
    const float T0 = trans[n * 3], T1 = trans[n * 3 + 1], T2 = trans[n * 3 + 2];
    const float* src; float* dst; int li;
    if (t < 48)      { src = g_QP + n * 144; dst = g_QG + n * 144; li = t; }
    else if (t < 96) { src = g_KP + n * 144; dst = g_KG + n * 144; li = t - 48; }
    else             { src = g_VP + n * 288; dst = g_VG + n * 288; li = t - 96; }
    float p0 = src[li * 3], p1 = src[li * 3 + 1], p2 = src[li * 3 + 2];
    dst[li * 3 + 0] = R[0] * p0 + R[1] * p1 + R[2] * p2 + T0;
    dst[li * 3 + 1] = R[3] * p0 + R[4] * p1 + R[5] * p2 + T1;
    dst[li * 3 + 2] = R[6] * p0 + R[7] * p1 + R[8] * p2 + T2;
}

// ---------------- kT2: transpose K (512x192) and KG (512x144) (validated) ----------------
__global__ void __launch_bounds__(256) kT2()
{
    __shared__ float tile[32][33];
    const int which = blockIdx.z;
    const float* src = which ? g_KG : g_K;
    float* dst = which ? g_KGT : g_KT;
    const int C = which ? 144 : 192;
    const int m0 = blockIdx.x * 32;
    const int c0 = blockIdx.y * 32;
    if (c0 >= C) return;
    const int tx = threadIdx.x & 31, ty = threadIdx.x >> 5;   // 32 x 8
    #pragma unroll
    for (int i = ty; i < 32; i += 8)
        if (c0 + tx < C)
            tile[i][tx] = src[(size_t)(m0 + i) * C + c0 + tx];
    __syncthreads();
    #pragma unroll
    for (int i = ty; i < 32; i += 8)
        if (c0 + i < C)
            dst[(size_t)(c0 + i) * 512 + m0 + tx] = tile[tx][i];
}

// ---------------- kFuse4: phase P (broadcast z.Wb) + fused L+S + phase A ----------------
__device__ __forceinline__ void cpAsync16(float* dst, const float* src)
{
    unsigned d = (unsigned)__cvta_generic_to_shared(dst);
    asm volatile("cp.async.cg.shared.global [%0], [%1], 16;" :: "r"(d), "l"(src));
}
#define CP_COMMIT() asm volatile("cp.async.commit_group;")
#define CP_WAIT1()  asm volatile("cp.async.wait_group 1;")
#define CP_WAIT0()  asm volatile("cp.async.wait_group 0;")

// dynamic smem layout (floats)
#define ZT_O  0        // 2 buf x 2 nn x 32 x 132 = 16896
#define LT_O  16896    // 2 nn x 416
#define PB_O  17728    // 2 nn x 416  (pair-bias staging, stride 13)
#define Q_O   18560    // 2 x 192
#define QG_O  18944    // 2 x 144
#define WB_O  19232    // 1536
#define DE_O  20768    // 768
#define PH_O  21536    // 36
#define HW_O  21572    // 12
#define FAC_O 21584    // 2 x 12
#define RMX_O 21608    // 2 x 12
#define RSM_O 21632    // 2 x 12
#define BB_O  21656    // 12
#define TR_O  21668    // 1536 (trans staged)
#define F4_SMEM 23204

__global__ void __launch_bounds__(512, 2) kFuse4(
    const float* __restrict__ z, const float* __restrict__ trans,
    const float* __restrict__ rot,
    const float* __restrict__ Wb, const float* __restrict__ bb,
    const float* __restrict__ de, const float* __restrict__ sl,
    const float* __restrict__ hw)
{
    extern __shared__ float sm[];
    const int n0 = blockIdx.x * 2;
    const int t = threadIdx.x;
    const int wid = t >> 5, lane = t & 31;

    for (int i = t; i < 384; i += 512) sm[Q_O + i]  = g_Q[(size_t)(n0 + i / 192) * 192 + i % 192];
    for (int i = t; i < 288; i += 512) sm[QG_O + i] = g_QG[(size_t)(n0 + i / 144) * 144 + i % 144];
    for (int i = t; i < 1536; i += 512) sm[WB_O + i] = Wb[i];
    for (int i = t; i < 768; i += 512) sm[DE_O + i] = de[i];
    for (int i = t; i < 1536; i += 512) sm[TR_O + i] = trans[i];
    if (t < 12) {
        sm[HW_O + t] = hw[t];
        sm[BB_O + t] = bb[t];
        sm[RMX_O + t] = -1e30f; sm[RMX_O + 12 + t] = -1e30f;
        sm[RSM_O + t] = 0.f;    sm[RSM_O + 12 + t] = 0.f;
        float a = sl[t], b2 = sl[12 + t], c = sl[24 + t];
        float mx = fmaxf(a, fmaxf(b2, c));
        float ea = expf(a - mx), eb = expf(b2 - mx), ec = expf(c - mx);
        float inv = 1.f / (ea + eb + ec);
        sm[PH_O + t] = ea * inv; sm[PH_O + 12 + t] = eb * inv; sm[PH_O + 24 + t] = ec * inv;
    }
    float tn[2][3];
    #pragma unroll
    for (int nn = 0; nn < 2; nn++) {
        tn[nn][0] = trans[(n0 + nn) * 3];
        tn[nn][1] = trans[(n0 + nn) * 3 + 1];
        tn[nn][2] = trans[(n0 + nn) * 3 + 2];
    }

    // prefetch tile 0
    {
        #pragma unroll
        for (int ii = 0; ii < 4; ii++) {
            int i4 = t + 512 * ii;
            int nn = i4 >> 10, mm = (i4 >> 5) & 31, c4 = i4 & 31;
            cpAsync16(sm + ZT_O + nn * 4224 + mm * 132 + c4 * 4,
                      z + ((size_t)(n0 + nn) * 512 + mm) * 128 + c4 * 4);
        }
        CP_COMMIT();
    }
    __syncthreads();

    // roles for phase A (validated)
    const int hb = wid * 3;
    const int cq = lane * 4;
    float pacc[2][3][4];
    #pragma unroll
    for (int nn = 0; nn < 2; nn++)
        #pragma unroll
        for (int i = 0; i < 3; i++)
            #pragma unroll
            for (int j = 0; j < 4; j++) pacc[nn][i][j] = 0.f;
    const int js = t - 128;
    const int hs = (js >= 0) ? js / 16 : 0;
    float sacc[2] = {0.f, 0.f};
    const int jp = t - 320;
    const int hp = (jp >= 0) ? jp / 8 : 0;
    float ap[2][3];
    #pragma unroll
    for (int nn = 0; nn < 2; nn++) { ap[nn][0] = 0.f; ap[nn][1] = 0.f; ap[nn][2] = 0.f; }
    const int Pm = t / 12, Ph = t % 12;   // phase-P slot (t<384)

    for (int mt = 0; mt < 16; mt++) {
        const int m0 = mt * 32;
        const int cur = mt & 1;
        float* ztc = sm + ZT_O + cur * 8448;
        if (mt < 15) {
            float* ztn = sm + ZT_O + (1 - cur) * 8448;
            const int mb = m0 + 32;
            #pragma unroll
            for (int ii = 0; ii < 4; ii++) {
                int i4 = t + 512 * ii;
                int nn = i4 >> 10, mm = (i4 >> 5) & 31, c4 = i4 & 31;
                cpAsync16(ztn + nn * 4224 + mm * 132 + c4 * 4,
                          z + ((size_t)(n0 + nn) * 512 + mb + mm) * 128 + c4 * 4);
            }
            CP_COMMIT();
            CP_WAIT1();
        } else {
            CP_WAIT0();
        }
        __syncthreads();

        // ---- phase P: z.Wb via broadcast mapping (m = t/12, h = t%12) ----
        if (t < 384) {
            float pb0 = sm[BB_O + Ph], pb1 = pb0;
            const float* zr0 = ztc + Pm * 132;
            const float* zr1 = ztc + 4224 + Pm * 132;
            #pragma unroll 8
            for (int c4 = 0; c4 < 32; c4++) {
                const float* w = &sm[WB_O + c4 * 48];
                float w0 = w[Ph], w1 = w[12 + Ph], w2 = w[24 + Ph], w3 = w[36 + Ph];
                float4 a = *(const float4*)(zr0 + c4 * 4);
                float4 b = *(const float4*)(zr1 + c4 * 4);
                pb0 += a.x * w0 + a.y * w1 + a.z * w2 + a.w * w3;
                pb1 += b.x * w0 + b.y * w1 + b.z * w2 + b.w * w3;
            }
            sm[PB_O + Pm * 13 + Ph]       = pb0;
            sm[PB_O + 416 + Pm * 13 + Ph] = pb1;
        }
        __syncthreads();

        // ---- fused phase L+S: warp = head, lane = m (validated; pb from smem) ----
        if (wid < 12) {
            const int h = wid;
            const int m = m0 + lane;
            float krv[16], kgv[12];
            #pragma unroll
            for (int c = 0; c < 16; c++) krv[c] = g_KT[(size_t)(h * 16 + c) * 512 + m];
            #pragma unroll
            for (int i = 0; i < 12; i++) kgv[i] = g_KGT[(size_t)(h * 12 + i) * 512 + m];
            const float tm0 = sm[TR_O + m * 3], tm1 = sm[TR_O + m * 3 + 1], tm2 = sm[TR_O + m * 3 + 2];
            #pragma unroll
            for (int nn = 0; nn < 2; nn++) {
                float dx = tn[nn][0] - tm0;
                float dy = tn[nn][1] - tm1;
                float dz = tn[nn][2] - tm2;
                float d  = sqrtf(dx * dx + dy * dy + dz * dz);
                int bin = min(max((int)ceilf(d * 2.0f) - 1, 0), 63);
                float lo = (d <= 5.0f) ? 1.f : 0.f;
                float me = (d > 5.0f && d <= 15.0f) ? 1.f : 0.f;
                float sc = 0.f;
                #pragma unroll
                for (int c = 0; c < 16; c++) sc += sm[Q_O + nn * 192 + h * 16 + c] * krv[c];
                float pd = 0.f;
                #pragma unroll
                for (int i = 0; i < 12; i++) {
                    float df = sm[QG_O + nn * 144 + h * 12 + i] - kgv[i];
                    pd += df * df;
                }
                float l = 0.25f * sc - 0.5f * pd * sm[HW_O + h]
                        + sm[PB_O + nn * 416 + lane * 13 + h]
                        + sm[DE_O + bin * 12 + h]
                        + lo * sm[PH_O + h] + me * sm[PH_O + 12 + h] + sm[PH_O + 24 + h];
                float tmax = l;
                #pragma unroll
                for (int o = 16; o; o >>= 1) tmax = fmaxf(tmax, __shfl_xor_sync(0xffffffffu, tmax, o));
                float om = sm[RMX_O + nn * 12 + h];
                float nm = fmaxf(om, tmax);
                float p = expf(l - nm);
                float tsum = p;
                #pragma unroll
                for (int o = 16; o; o >>= 1) tsum += __shfl_xor_sync(0xffffffffu, tsum, o);
                sm[LT_O + nn * 416 + lane * 13 + h] = p;
                if (lane == 0) {
                    float f = expf(om - nm);
                    sm[RMX_O + nn * 12 + h] = nm;
                    sm[RSM_O + nn * 12 + h] = sm[RSM_O + nn * 12 + h] * f + tsum;
                    sm[FAC_O + nn * 12 + h] = f;
                }
            }
        }
        __syncthreads();

        // ---- phase A: rescale + accumulate (validated, unchanged) ----
        if (t < 128) {
            #pragma unroll
            for (int nn = 0; nn < 2; nn++)
                #pragma unroll
                for (int hh = 0; hh < 3; hh++) {
                    float f = sm[FAC_O + nn * 12 + hb + hh];
                    #pragma unroll
                    for (int j = 0; j < 4; j++) pacc[nn][hh][j] *= f;
                }
            #pragma unroll 4
            for (int mm = 0; mm < 32; mm++) {
                #pragma unroll
                for (int nn = 0; nn < 2; nn++) {
                    float4 zz = *(const float4*)(ztc + nn * 4224 + mm * 132 + cq);
                    const float* pr = sm + LT_O + nn * 416 + mm * 13 + hb;
                    #pragma unroll
                    for (int hh = 0; hh < 3; hh++) {
                        float p = pr[hh];
                        pacc[nn][hh][0] += p * zz.x; pacc[nn][hh][1] += p * zz.y;
                        pacc[nn][hh][2] += p * zz.z; pacc[nn][hh][3] += p * zz.w;
                    }
                }
            }
        } else if (t < 320) {
            sacc[0] *= sm[FAC_O + hs];
            sacc[1] *= sm[FAC_O + 12 + hs];
            #pragma unroll 8
            for (int mm = 0; mm < 32; mm++) {
                float v = g_V[(size_t)(m0 + mm) * 192 + js];
                sacc[0] += sm[LT_O + mm * 13 + hs] * v;
                sacc[1] += sm[LT_O + 416 + mm * 13 + hs] * v;
            }
        } else if (t < 416) {
            #pragma unroll
            for (int nn = 0; nn < 2; nn++) {
                float f = sm[FAC_O + nn * 12 + hp];
                ap[nn][0] *= f; ap[nn][1] *= f; ap[nn][2] *= f;
            }
            #pragma unroll 8
            for (int mm = 0; mm < 32; mm++) {
                const float* vg = g_VG + (size_t)(m0 + mm) * 288 + jp * 3;
                float v0 = vg[0], v1 = vg[1], v2 = vg[2];
                float p0 = sm[LT_O + mm * 13 + hp];
                float p1 = sm[LT_O + 416 + mm * 13 + hp];
                ap[0][0] += p0 * v0; ap[0][1] += p0 * v1; ap[0][2] += p0 * v2;
                ap[1][0] += p1 * v0; ap[1][1] += p1 * v1; ap[1][2] += p1 * v2;
            }
        }
        __syncthreads();
    }

    // epilogue (validated, per row)
    if (t < 24) sm[FAC_O + t] = 1.0f / sm[RSM_O + t];
    __syncthreads();
    if (t < 128) {
        #pragma unroll
        for (int nn = 0; nn < 2; nn++)
            #pragma unroll
            for (int hh = 0; hh < 3; hh++) {
                float inv = sm[FAC_O + nn * 12 + hb + hh];
                float4 v = {pacc[nn][hh][0] * inv, pacc[nn][hh][1] * inv,
                            pacc[nn][hh][2] * inv, pacc[nn][hh][3] * inv};
                *(float4*)(g_F + (size_t)(n0 + nn) * 2112 + (hb + hh) * 176 + 48 + cq) = v;
            }
    } else if (t < 320) {
        g_F[(size_t)n0 * 2112 + hs * 176 + (js % 16)]       = sacc[0] * sm[FAC_O + hs];
        g_F[(size_t)(n0 + 1) * 2112 + hs * 176 + (js % 16)] = sacc[1] * sm[FAC_O + 12 + hs];
    } else if (t < 416) {
        const int pp = jp % 8;
        #pragma unroll
        for (int nn = 0; nn < 2; nn++) {
            float inv = sm[FAC_O + nn * 12 + hp];
            float a0 = ap[nn][0] * inv - tn[nn][0];
            float a1 = ap[nn][1] * inv - tn[nn][1];
            float a2 = ap[nn][2] * inv - tn[nn][2];
            const float* R = rot + (n0 + nn) * 9;
            float lx = R[0] * a0 + R[3] * a1 + R[6] * a2;   // R^T
            float ly = R[1] * a0 + R[4] * a1 + R[7] * a2;
            float lz = R[2] * a0 + R[5] * a1 + R[8] * a2;
            float* Fh = g_F + (size_t)(n0 + nn) * 2112 + hp * 176;
            Fh[16 + pp * 3]     = lx;
            Fh[16 + pp * 3 + 1] = ly;
            Fh[16 + pp * 3 + 2] = lz;
            Fh[40 + pp]         = sqrtf(lx * lx + ly * ly + lz * lz);
        }
    }
}

// ---------------- kOut: tiled split-K GEMM 512x384, K=2112 split 12x176 ----------------
__global__ void __launch_bounds__(256) kOut(const float* __restrict__ Wout)
{
    __shared__ float As[16 * 68];
    __shared__ float Bs[16 * 68];
    const int t  = threadIdx.x;
    const int c0 = blockIdx.x * 64;
    const int r0 = blockIdx.y * 64;
    const int k0 = blockIdx.z * 176;
    const int tx = t % 16, ty = t / 16;
    float acc[4][4];
    #pragma unroll
    for (int i = 0; i < 4; i++)
        #pragma unroll
        for (int j = 0; j < 4; j++) acc[i][j] = 0.f;

    for (int kt = 0; kt < 11; kt++) {
        const int kb = k0 + kt * 16;
        __syncthreads();
        #pragma unroll
        for (int ii = 0; ii < 4; ii++) {
            int i = t + 256 * ii;
            int row = i >> 4, k = i & 15;
            As[k * 68 + row] = g_F[(size_t)(r0 + row) * 2112 + kb + k];
        }
        #pragma unroll
        for (int ii = 0; ii < 4; ii++) {
            int i = t + 256 * ii;
            int k = i >> 6, c = i & 63;
            Bs[k * 68 + c] = Wout[(size_t)(kb + k) * 384 + c0 + c];
        }
        __syncthreads();
        #pragma unroll
        for (int k = 0; k < 16; k++) {
            float4 a = *(const float4*)&As[k * 68 + ty * 4];
            float4 b = *(const float4*)&Bs[k * 68 + tx * 4];
            float av[4] = {a.x, a.y, a.z, a.w};
            float bw[4] = {b.x, b.y, b.z, b.w};
            #pragma unroll
            for (int i = 0; i < 4; i++)
                #pragma unroll
                for (int j = 0; j < 4; j++) acc[i][j] += av[i] * bw[j];
        }
    }
    float* Pp = g_EP + (size_t)blockIdx.z * 512 * 384;
    #pragma unroll
    for (int i = 0; i < 4; i++) {
        float4 v = {acc[i][0], acc[i][1], acc[i][2], acc[i][3]};
        *(float4*)(Pp + (size_t)(r0 + ty * 4 + i) * 384 + c0 + tx * 4) = v;
    }
}

__global__ void __launch_bounds__(256) kOutRed(float* __restrict__ out,
                                               const float* __restrict__ bout)
{
    const int e = (blockIdx.x * 256 + threadIdx.x) * 4;
    float4 acc = *(const float4*)(bout + (e % 384));
    #pragma unroll
    for (int zz = 0; zz < 12; zz++) {
        float4 p = *(const float4*)(g_EP + (size_t)zz * 512 * 384 + e);
        acc.x += p.x; acc.y += p.y; acc.z += p.z; acc.w += p.w;
    }
    *(float4*)(out + e) = acc;
}

extern "C" void kernel_launch(void* const* d_in, const int* in_sizes, int n_in,
                              void* d_out, int out_size)
{
    const float* s     = (const float*)d_in[0];
    const float* z     = (const float*)d_in[1];
    const float* trans = (const float*)d_in[2];
    const float* rot   = (const float*)d_in[3];
    // d_in[4] = mask (all true; unused)
    const float* Wq  = (const float*)d_in[5];   const float* bq  = (const float*)d_in[6];
    const float* Wk  = (const float*)d_in[7];   const float* bk  = (const float*)d_in[8];
    const float* Wv  = (const float*)d_in[9];   const float* bv  = (const float*)d_in[10];
    const float* Wqp = (const float*)d_in[11];  const float* bqp = (const float*)d_in[12];
    const float* Wkp = (const float*)d_in[13];  const float* bkp = (const float*)d_in[14];
    const float* Wvp = (const float*)d_in[15];  const float* bvp = (const float*)d_in[16];
    const float* Wb  = (const float*)d_in[17];  const float* bb  = (const float*)d_in[18];
    const float* de  = (const float*)d_in[19];
    const float* sl  = (const float*)d_in[20];
    const float* hw  = (const float*)d_in[21];
    const float* Wout = (const float*)d_in[22];
    const float* bout = (const float*)d_in[23];
    float* out = (float*)d_out;

    cudaFuncSetAttribute(kFuse4, cudaFuncAttributeMaxDynamicSharedMemorySize,
                         F4_SMEM * 4);

    kProj<<<dim3(18, 8), 256>>>(s, Wq, bq, Wk, bk, Wv, bv, Wqp, bqp, Wkp, bkp, Wvp, bvp);
    pTrans<<<512, 192>>>(trans, rot);
    kT2<<<dim3(16, 6, 2), 256>>>();
    kFuse4<<<256, 512, F4_SMEM * 4>>>(z, trans, rot, Wb, bb, de, sl, hw);
    kOut<<<dim3(6, 8, 12), 256>>>(Wout);
    kOutRed<<<192, 256>>>(out, bout);
}